// round 9
// baseline (speedup 1.0000x reference)
#include <cuda_runtime.h>
#include <cstdint>

// Problem constants (fixed by the reference setup)
static constexpr int   N_PER_TABLE = 2097152;          // 2^21 indices/weights per table
static constexpr int   B_PER_TABLE = 8192;             // offsets used per table (input len B+1)
static constexpr int   T_TABLES    = 8;
static constexpr long long IDX_TOT = (long long)T_TABLES * N_PER_TABLE;     // 16777216
static constexpr long long OFF_TOT = (long long)T_TABLES * B_PER_TABLE + 1; // 65537
static constexpr int   NVEC        = N_PER_TABLE / 4;  // float4/int4 vectors per table = 2^19

static constexpr int   GRID     = 2048;
static constexpr int   BLOCK    = 256;
static constexpr int   NTHREADS = GRID * BLOCK;        // 2^19 == NVEC (load-bearing identity!)
static_assert(NTHREADS == NVEC, "grid geometry must match per-table vector count");

static constexpr long long W_TOT = IDX_TOT;            // 16777216 weights
static constexpr long long WVEC  = (W_TOT - 4) / 4;    // 4194303 aligned store vectors

struct TablePtrs {
    const int4*   idx[T_TABLES];
    const int*    off[T_TABLES];
    const float4* w[T_TABLES];
};

__global__ void __launch_bounds__(BLOCK)
tbe_prepare_kernel(TablePtrs p, float* __restrict__ out) {
    // Output: ONE float32 buffer [indices-as-float | offsets-as-float | weights]
    float4* out_idx = reinterpret_cast<float4*>(out);       // 256B-aligned base
    float*  out_off = out + IDX_TOT;
    float*  out_w   = out + IDX_TOT + OFF_TOT;              // byte addr ≡ 4 (mod 16)
    float4* out_w_v = reinterpret_cast<float4*>(out_w + 3); // 16B-aligned

    const int tid  = blockIdx.x * BLOCK + threadIdx.x;      // 0 .. 2^19-1
    const int lane = threadIdx.x & 31;

    // ---- indices: per-u table is COMPILE-TIME (t == u, j == tid) ----
    // 1 LDG.128 -> 4 exact I2F -> 1 STG.128 per table, 4-deep front-batched.
    #pragma unroll
    for (int ub = 0; ub < T_TABLES; ub += 4) {
        int4 v[4];
        #pragma unroll
        for (int q = 0; q < 4; ++q)
            v[q] = __ldcs(p.idx[ub + q] + tid);
        #pragma unroll
        for (int q = 0; q < 4; ++q) {
            float4 f;
            f.x = (float)v[q].x;  f.y = (float)v[q].y;
            f.z = (float)v[q].z;  f.w = (float)v[q].w;
            __stcs(&out_idx[(long long)(ub + q) * NTHREADS + tid], f);
        }
    }

    // ---- weights: aligned LDG.128 + warp-shuffle realignment -> aligned STG.128 ----
    // Store vector k = u*2^19 + tid covers elements [3+4k, 7+4k) =
    //   { v_k.w, v_{k+1}.x, v_{k+1}.y, v_{k+1}.z }.
    // Lanes 0-30 get v_{k+1} from shfl_down; lane 31 loads it (next j, or next table).
    #pragma unroll
    for (int ub = 0; ub < T_TABLES; ub += 4) {
        float4 v[4], nx[4];
        #pragma unroll
        for (int q = 0; q < 4; ++q) {
            const int u = ub + q;
            v[q] = __ldcs(p.w[u] + tid);
            if (lane == 31) {
                if (tid + 1 < NVEC)           nx[q] = __ldcs(p.w[u] + tid + 1);
                else if (u + 1 < T_TABLES)    nx[q] = __ldcs(p.w[u + 1]);       // table seam
                else                          nx[q] = v[q];                     // k==WVEC, store guarded off
            }
        }
        #pragma unroll
        for (int q = 0; q < 4; ++q) {
            float4 nv;
            nv.x = __shfl_down_sync(0xffffffffu, v[q].x, 1);
            nv.y = __shfl_down_sync(0xffffffffu, v[q].y, 1);
            nv.z = __shfl_down_sync(0xffffffffu, v[q].z, 1);
            if (lane == 31) nv = nx[q];
            float4 s;
            s.x = v[q].w;  s.y = nv.x;  s.z = nv.y;  s.w = nv.z;
            const long long k = (long long)(ub + q) * NTHREADS + tid;
            if (k < WVEC) __stcs(&out_w_v[k], s);
        }
    }

    // ---- weight prologue (elements 0..2) + tail (element W_TOT-1) ----
    if (tid < 3) {
        out_w[tid] = __ldcs(&p.w[0][0].x + tid);
    } else if (tid == 3) {
        out_w[W_TOT - 1] = __ldcs(&p.w[T_TABLES - 1][NVEC - 1].w);
    }

    // ---- offsets: first B entries per table, rebased by t*N, stored as float ----
    const int OFF_WORK = T_TABLES * B_PER_TABLE;    // 65536
    if (tid < OFF_WORK) {
        const int t = tid >> 13;                    // / 8192
        const int j = tid & (B_PER_TABLE - 1);
        out_off[tid] = (float)(p.off[t][j] + t * N_PER_TABLE);
    }
    if (tid == 0) {
        out_off[OFF_WORK] = (float)IDX_TOT;         // grand total (2^24, exact in fp32)
    }
}

extern "C" void kernel_launch(void* const* d_in, const int* in_sizes, int n_in,
                              void* d_out, int out_size) {
    (void)out_size;

    TablePtrs p;

    // Runtime layout detection via the distinctive offsets length (B+1 = 8193).
    // Grouped:     indices_0..7, offsets_0..7, weights_0..7
    // Interleaved: indices_0, offsets_0, weights_0, indices_1, ...
    const bool grouped = (n_in >= 24) && (in_sizes[8] == B_PER_TABLE + 1);

    if (grouped) {
        for (int t = 0; t < T_TABLES; ++t) {
            p.idx[t] = reinterpret_cast<const int4*>(d_in[t]);
            p.off[t] = reinterpret_cast<const int*>(d_in[T_TABLES + t]);
            p.w[t]   = reinterpret_cast<const float4*>(d_in[2 * T_TABLES + t]);
        }
    } else {
        for (int t = 0; t < T_TABLES; ++t) {
            p.idx[t] = reinterpret_cast<const int4*>(d_in[3 * t + 0]);
            p.off[t] = reinterpret_cast<const int*>(d_in[3 * t + 1]);
            p.w[t]   = reinterpret_cast<const float4*>(d_in[3 * t + 2]);
        }
    }

    tbe_prepare_kernel<<<GRID, BLOCK>>>(p, reinterpret_cast<float*>(d_out));
}

// round 10
// speedup vs baseline: 1.0049x; 1.0049x over previous
#include <cuda_runtime.h>
#include <cstdint>

// Problem constants (fixed by the reference setup)
static constexpr int   N_PER_TABLE = 2097152;          // 2^21 indices/weights per table
static constexpr int   B_PER_TABLE = 8192;             // offsets used per table (input len B+1)
static constexpr int   T_TABLES    = 8;
static constexpr long long IDX_TOT = (long long)T_TABLES * N_PER_TABLE;     // 16777216
static constexpr long long OFF_TOT = (long long)T_TABLES * B_PER_TABLE + 1; // 65537
static constexpr int   NVEC        = N_PER_TABLE / 4;  // float4/int4 vectors per table = 2^19

static constexpr int   GRID     = 4096;
static constexpr int   BLOCK    = 128;
static constexpr int   NTHREADS = GRID * BLOCK;        // 2^19 == NVEC (load-bearing identity!)
static_assert(NTHREADS == NVEC, "grid geometry must match per-table vector count");

static constexpr long long W_TOT = IDX_TOT;            // 16777216 weights
static constexpr long long WVEC  = (W_TOT - 4) / 4;    // 4194303 aligned store vectors

struct TablePtrs {
    const int4*   idx[T_TABLES];
    const int*    off[T_TABLES];
    const float4* w[T_TABLES];
};

__global__ void __launch_bounds__(BLOCK)
tbe_prepare_kernel(TablePtrs p, float* __restrict__ out) {
    // Output: ONE float32 buffer [indices-as-float | offsets-as-float | weights]
    float4* out_idx = reinterpret_cast<float4*>(out);       // 256B-aligned base
    float*  out_off = out + IDX_TOT;
    float*  out_w   = out + IDX_TOT + OFF_TOT;              // byte addr ≡ 4 (mod 16)
    float4* out_w_v = reinterpret_cast<float4*>(out_w + 3); // 16B-aligned

    const int tid  = blockIdx.x * BLOCK + threadIdx.x;      // 0 .. 2^19-1
    const int lane = threadIdx.x & 31;

    // Interleaved copy: per table u, one idx vector (with exact I2F) and one
    // realigned weights vector. t == u is compile-time; j == tid.
    //
    // Weights realignment (1 shuffle): output store vector k = u*2^19 + tid covers
    // elements [3+4k, 7+4k) = { vec_k.w, vec_{k+1}.x, vec_{k+1}.y, vec_{k+1}.z }.
    // Lane l loads vec_{k+1}; lane l-1's load IS vec_k, so vec_k.w arrives via
    // shfl_up(…,1). Lane 0 fetches vec_k.w with one scalar load.
    #pragma unroll
    for (int ub = 0; ub < T_TABLES; ub += 2) {
        int4   vi[2];
        float4 vw[2];
        float  w3[2];

        #pragma unroll
        for (int q = 0; q < 2; ++q) {
            const int u = ub + q;
            vi[q] = __ldcs(p.idx[u] + tid);

            // weights: load flat vector (u*2^19 + tid + 1)
            if (tid == NVEC - 1) {
                if (u + 1 < T_TABLES) vw[q] = __ldcs(p.w[u + 1]);   // table seam
                else                  vw[q] = make_float4(0.f, 0.f, 0.f, 0.f); // k==WVEC, store guarded
            } else {
                vw[q] = __ldcs(p.w[u] + tid + 1);
            }
            if (lane == 0) {
                // vec_k.w for this lane (k = u*2^19 + tid, table u, slot tid)
                w3[q] = __ldcs(reinterpret_cast<const float*>(p.w[ub + q]) + 4 * tid + 3);
            }
        }

        #pragma unroll
        for (int q = 0; q < 2; ++q) {
            const int u = ub + q;

            float4 f;
            f.x = (float)vi[q].x;  f.y = (float)vi[q].y;
            f.z = (float)vi[q].z;  f.w = (float)vi[q].w;
            __stcs(&out_idx[(long long)u * NTHREADS + tid], f);

            float prev_w = __shfl_up_sync(0xffffffffu, vw[q].w, 1);
            if (lane == 0) prev_w = w3[q];
            float4 s;
            s.x = prev_w;  s.y = vw[q].x;  s.z = vw[q].y;  s.w = vw[q].z;
            const long long k = (long long)u * NTHREADS + tid;
            if (k < WVEC) __stcs(&out_w_v[k], s);
        }
    }

    // ---- weight prologue (elements 0..2) + tail (element W_TOT-1) ----
    if (tid < 3) {
        out_w[tid] = __ldcs(reinterpret_cast<const float*>(p.w[0]) + tid);
    } else if (tid == 3) {
        out_w[W_TOT - 1] = __ldcs(reinterpret_cast<const float*>(p.w[T_TABLES - 1]) + N_PER_TABLE - 1);
    }

    // ---- offsets: first B entries per table, rebased by t*N, stored as float ----
    const int OFF_WORK = T_TABLES * B_PER_TABLE;    // 65536
    if (tid < OFF_WORK) {
        const int t = tid >> 13;                    // / 8192
        const int j = tid & (B_PER_TABLE - 1);
        out_off[tid] = (float)(p.off[t][j] + t * N_PER_TABLE);
    }
    if (tid == 0) {
        out_off[OFF_WORK] = (float)IDX_TOT;         // grand total (2^24, exact in fp32)
    }
}

extern "C" void kernel_launch(void* const* d_in, const int* in_sizes, int n_in,
                              void* d_out, int out_size) {
    (void)out_size;

    TablePtrs p;

    // Runtime layout detection via the distinctive offsets length (B+1 = 8193).
    // Grouped:     indices_0..7, offsets_0..7, weights_0..7
    // Interleaved: indices_0, offsets_0, weights_0, indices_1, ...
    const bool grouped = (n_in >= 24) && (in_sizes[8] == B_PER_TABLE + 1);

    if (grouped) {
        for (int t = 0; t < T_TABLES; ++t) {
            p.idx[t] = reinterpret_cast<const int4*>(d_in[t]);
            p.off[t] = reinterpret_cast<const int*>(d_in[T_TABLES + t]);
            p.w[t]   = reinterpret_cast<const float4*>(d_in[2 * T_TABLES + t]);
        }
    } else {
        for (int t = 0; t < T_TABLES; ++t) {
            p.idx[t] = reinterpret_cast<const int4*>(d_in[3 * t + 0]);
            p.off[t] = reinterpret_cast<const int*>(d_in[3 * t + 1]);
            p.w[t]   = reinterpret_cast<const float4*>(d_in[3 * t + 2]);
        }
    }

    tbe_prepare_kernel<<<GRID, BLOCK>>>(p, reinterpret_cast<float*>(d_out));
}

// round 11
// speedup vs baseline: 1.0142x; 1.0092x over previous
#include <cuda_runtime.h>
#include <cstdint>

// Problem constants (fixed by the reference setup)
static constexpr int   N_PER_TABLE = 2097152;          // 2^21 indices/weights per table
static constexpr int   B_PER_TABLE = 8192;             // offsets used per table (input len B+1)
static constexpr int   T_TABLES    = 8;
static constexpr long long IDX_TOT = (long long)T_TABLES * N_PER_TABLE;     // 16777216
static constexpr long long OFF_TOT = (long long)T_TABLES * B_PER_TABLE + 1; // 65537
static constexpr int   NVEC        = N_PER_TABLE / 4;  // float4/int4 vectors per table = 2^19

static constexpr int   GRID     = 2048;
static constexpr int   BLOCK    = 256;
static constexpr int   NTHREADS = GRID * BLOCK;        // 2^19 == NVEC (load-bearing identity!)
static_assert(NTHREADS == NVEC, "grid geometry must match per-table vector count");

static constexpr long long W_TOT = IDX_TOT;            // 16777216 weights
static constexpr long long WVEC  = (W_TOT - 4) / 4;    // 4194303 aligned store vectors

struct TablePtrs {
    const int4*   idx[T_TABLES];
    const int*    off[T_TABLES];
    const float4* w[T_TABLES];
};

__global__ void __launch_bounds__(BLOCK)
tbe_prepare_kernel(TablePtrs p, float* __restrict__ out) {
    // Output: ONE float32 buffer [indices-as-float | offsets-as-float | weights]
    float4* out_idx = reinterpret_cast<float4*>(out);       // 256B-aligned base
    float*  out_off = out + IDX_TOT;
    float*  out_w   = out + IDX_TOT + OFF_TOT;              // byte addr ≡ 4 (mod 16)
    float4* out_w_v = reinterpret_cast<float4*>(out_w + 3); // 16B-aligned

    const int tid  = blockIdx.x * BLOCK + threadIdx.x;      // 0 .. 2^19-1
    const int lane = threadIdx.x & 31;
    const bool last_vec = (tid == NVEC - 1);

    // Deep front-batched copy: 4 tables per iteration => 8 LDG.128 (+ lane-0
    // scalars) in flight before any store. t == u is compile-time; j == tid.
    //
    // Weights realignment (1 shuffle): output store vector k = u*2^19 + tid covers
    // elements [3+4k, 7+4k) = { vec_k.w, vec_{k+1}.x, vec_{k+1}.y, vec_{k+1}.z }.
    // Lane l loads vec_{k+1}; lane l-1's load IS vec_k, so vec_k.w arrives via
    // shfl_up(…,1). Lane 0 fetches vec_k.w with one scalar load.
    #pragma unroll
    for (int ub = 0; ub < T_TABLES; ub += 4) {
        int4   vi[4];
        float4 vw[4];
        float  w3[4];

        #pragma unroll
        for (int q = 0; q < 4; ++q) {
            const int u = ub + q;
            vi[q] = __ldcs(p.idx[u] + tid);

            // weights: flat vector (u*2^19 + tid + 1); at the table seam the
            // next vector is the first vector of table u+1 (or dummy at the end,
            // where the store is guarded off by k < WVEC).
            const float4* wsrc;
            if (last_vec) wsrc = (u + 1 < T_TABLES) ? p.w[u + 1] : p.w[u];
            else          wsrc = p.w[u] + (tid + 1);
            vw[q] = __ldcs(wsrc);

            if (lane == 0) {
                // vec_k.w for this lane (k = u*2^19 + tid, table u, slot tid)
                w3[q] = __ldcs(reinterpret_cast<const float*>(p.w[u]) + 4 * tid + 3);
            }
        }

        #pragma unroll
        for (int q = 0; q < 4; ++q) {
            const int u = ub + q;

            float4 f;
            f.x = (float)vi[q].x;  f.y = (float)vi[q].y;
            f.z = (float)vi[q].z;  f.w = (float)vi[q].w;
            __stcs(&out_idx[(long long)u * NTHREADS + tid], f);

            float prev_w = __shfl_up_sync(0xffffffffu, vw[q].w, 1);
            if (lane == 0) prev_w = w3[q];
            float4 s;
            s.x = prev_w;  s.y = vw[q].x;  s.z = vw[q].y;  s.w = vw[q].z;
            const long long k = (long long)u * NTHREADS + tid;
            if (k < WVEC) __stcs(&out_w_v[k], s);
        }
    }

    // ---- weight prologue (elements 0..2) + tail (element W_TOT-1) ----
    if (tid < 3) {
        out_w[tid] = __ldcs(reinterpret_cast<const float*>(p.w[0]) + tid);
    } else if (tid == 3) {
        out_w[W_TOT - 1] = __ldcs(reinterpret_cast<const float*>(p.w[T_TABLES - 1]) + N_PER_TABLE - 1);
    }

    // ---- offsets: first B entries per table, rebased by t*N, stored as float ----
    const int OFF_WORK = T_TABLES * B_PER_TABLE;    // 65536
    if (tid < OFF_WORK) {
        const int t = tid >> 13;                    // / 8192
        const int j = tid & (B_PER_TABLE - 1);
        out_off[tid] = (float)(p.off[t][j] + t * N_PER_TABLE);
    }
    if (tid == 0) {
        out_off[OFF_WORK] = (float)IDX_TOT;         // grand total (2^24, exact in fp32)
    }
}

extern "C" void kernel_launch(void* const* d_in, const int* in_sizes, int n_in,
                              void* d_out, int out_size) {
    (void)out_size;

    TablePtrs p;

    // Runtime layout detection via the distinctive offsets length (B+1 = 8193).
    // Grouped:     indices_0..7, offsets_0..7, weights_0..7
    // Interleaved: indices_0, offsets_0, weights_0, indices_1, ...
    const bool grouped = (n_in >= 24) && (in_sizes[8] == B_PER_TABLE + 1);

    if (grouped) {
        for (int t = 0; t < T_TABLES; ++t) {
            p.idx[t] = reinterpret_cast<const int4*>(d_in[t]);
            p.off[t] = reinterpret_cast<const int*>(d_in[T_TABLES + t]);
            p.w[t]   = reinterpret_cast<const float4*>(d_in[2 * T_TABLES + t]);
        }
    } else {
        for (int t = 0; t < T_TABLES; ++t) {
            p.idx[t] = reinterpret_cast<const int4*>(d_in[3 * t + 0]);
            p.off[t] = reinterpret_cast<const int*>(d_in[3 * t + 1]);
            p.w[t]   = reinterpret_cast<const float4*>(d_in[3 * t + 2]);
        }
    }

    tbe_prepare_kernel<<<GRID, BLOCK>>>(p, reinterpret_cast<float*>(d_out));
}